// round 10
// baseline (speedup 1.0000x reference)
#include <cuda_runtime.h>
#include <math.h>

// ---------------------------------------------------------------------------
// ANI ensemble MLP energy on GB300 (packed fma.rn.f32x2, split-k warp pairs).
// 2-launch cycle: k_bin -> k_compute. Last compute block writes the scalar
// and resets device globals (statics zero-init for call #1).
// Output = sum_a mean_e net_{species[a]}^{(e)}(aev[a]).
// ---------------------------------------------------------------------------

#define NMAX 100000
constexpr int S_ = 4;
constexpr int E_ = 8;
constexpr int D0 = 384, D1 = 160, D2 = 128, D3 = 96;
constexpr int TM = 64;        // atoms per block
constexpr int PAD = 68;       // smem activation row stride (floats)
constexpr int KC = 16;        // K-chunk for weight staging
constexpr int NT = 512;       // 16 warps = 8 output groups x 2 k-halves
constexpr int BUFF = KC * D1; // floats per weight buffer (max-N chunk) = 2560

using u64 = unsigned long long;

__device__ int    g_cnt[S_];      // zero-initialized
__device__ int    g_idx[S_ * NMAX];
__device__ double g_sum;          // zero-initialized
__device__ int    g_done;         // zero-initialized

__global__ void k_bin(const int* __restrict__ species, int n) {
    int i = blockIdx.x * blockDim.x + threadIdx.x;
    int lane = threadIdx.x & 31;
    unsigned active = __ballot_sync(0xffffffffu, i < n);
    if (i < n) {
        int s = species[i] & (S_ - 1);
        unsigned peers = __match_any_sync(active, s);
        int leader = __ffs(peers) - 1;
        int rank = __popc(peers & ((1u << lane) - 1));
        int base = 0;
        if (lane == leader) base = atomicAdd(&g_cnt[s], __popc(peers));
        base = __shfl_sync(peers, base, leader);
        g_idx[s * NMAX + base + rank] = i;
    }
}

__device__ __forceinline__ float celu_f(float x) {
    // jax.nn.celu(x, 0.1) = x>0 ? x : 0.1*expm1(x/0.1)
    return x > 0.0f ? x : 0.1f * expm1f(x * 10.0f);
}

__device__ __forceinline__ u64 splat2(float x) {
    u64 r; asm("mov.b64 %0, {%1, %1};" : "=l"(r) : "f"(x)); return r;
}
__device__ __forceinline__ u64 fma2(u64 a, u64 b, u64 c) {
    u64 d; asm("fma.rn.f32x2 %0, %1, %2, %3;" : "=l"(d) : "l"(a), "l"(b), "l"(c));
    return d;
}
__device__ __forceinline__ u64 fadd2(u64 a, u64 b) {
    u64 d; asm("add.rn.f32x2 %0, %1, %2;" : "=l"(d) : "l"(a), "l"(b));
    return d;
}
__device__ __forceinline__ float2 unpk(u64 a) {
    float2 f; asm("mov.b64 {%0, %1}, %2;" : "=f"(f.x), "=f"(f.y) : "l"(a));
    return f;
}

__device__ __forceinline__ void cp16(float* smem_dst, const float4* gsrc) {
    unsigned a = (unsigned)__cvta_generic_to_shared(smem_dst);
    asm volatile("cp.async.cg.shared.global [%0], [%1], 16;\n" :: "r"(a), "l"(gsrc));
}
__device__ __forceinline__ void cp_commit() {
    asm volatile("cp.async.commit_group;\n");
}

// One dense layer with split-k: sOut[n][atom] = celu(sIn @ gW + sB).
// Warps 0-7 (half=0): output group wg, k in [0, K/2).
// Warps 8-15 (half=1): same output groups, k in [K/2, K).
// acc[atom][j] packs outputs (2j, 2j+1) of group base TN*wg.
// Partials combined through scratch (= the 4 weight buffers) at the epilogue.
template<int K, int N, int TN>
__device__ __forceinline__ void gemm_layer(
    const float* __restrict__ sIn, const float* __restrict__ gW,
    const float* __restrict__ sB, float* __restrict__ sOut,
    float* __restrict__ sWB, int tid, int lane, int wid) {

    constexpr int TNH = TN / 2;
    static_assert((TNH & 1) == 0, "TNH even: float4 weight loads");
    constexpr int C   = K / KC;        // total chunks
    constexpr int H   = C / 2;         // chunks per half
    static_assert(C % 2 == 0, "even chunk count for split-k");
    constexpr int NV4 = KC * N / 4;    // float4 per chunk

    const int half = wid >> 3;         // 0 = lower k, 1 = upper k
    const int wg   = wid & 7;          // output group

    u64 acc[2][TNH];
#pragma unroll
    for (int a = 0; a < 2; a++)
#pragma unroll
        for (int j = 0; j < TNH; j++) acc[a][j] = 0ull;

    const float4* gW4 = reinterpret_cast<const float4*>(gW);
    float* bL[2] = { sWB,            sWB + BUFF     };
    float* bU[2] = { sWB + 2 * BUFF, sWB + 3 * BUFF };

    // prefetch step 0: lower chunk 0 + upper chunk H (one cp.async group)
    for (int l = tid; l < NV4; l += NT) cp16(bL[0] + 4 * l, gW4 + l);
    for (int l = tid; l < NV4; l += NT) cp16(bU[0] + 4 * l, gW4 + (size_t)H * NV4 + l);
    cp_commit();

    int p = 0;
    for (int t = 0; t < H; t++) {
        if (t + 1 < H) {
            const float4* sL = gW4 + (size_t)(t + 1) * NV4;
            const float4* sU = gW4 + (size_t)(H + t + 1) * NV4;
            float* dL = bL[p ^ 1];
            float* dU = bU[p ^ 1];
            for (int l = tid; l < NV4; l += NT) cp16(dL + 4 * l, sL + l);
            for (int l = tid; l < NV4; l += NT) cp16(dU + 4 * l, sU + l);
            cp_commit();
            asm volatile("cp.async.wait_group 1;\n");
        } else {
            asm volatile("cp.async.wait_group 0;\n");
        }
        __syncthreads();

        const float* sW = half ? bU[p] : bL[p];
        const float* inBase = sIn + (half * H + t) * KC * PAD + 2 * lane;
#pragma unroll 4
        for (int kk = 0; kk < KC; kk++) {
            float2 av = *reinterpret_cast<const float2*>(inBase + kk * PAD);
            u64 a0 = splat2(av.x);
            u64 a1 = splat2(av.y);
            const ulonglong2* wr =
                reinterpret_cast<const ulonglong2*>(sW + kk * N + TN * wg);
#pragma unroll
            for (int j2 = 0; j2 < TNH / 2; j2++) {
                ulonglong2 w2 = wr[j2];
                acc[0][2 * j2]     = fma2(a0, w2.x, acc[0][2 * j2]);
                acc[1][2 * j2]     = fma2(a1, w2.x, acc[1][2 * j2]);
                acc[0][2 * j2 + 1] = fma2(a0, w2.y, acc[0][2 * j2 + 1]);
                acc[1][2 * j2 + 1] = fma2(a1, w2.y, acc[1][2 * j2 + 1]);
            }
        }
        __syncthreads();
        p ^= 1;
    }

    // ---- combine halves: upper warps dump partials into scratch (= buffers)
    u64* scratch = reinterpret_cast<u64*>(sWB);   // 8*2*TNH*32 u64 <= 40960 B
    if (half) {
#pragma unroll
        for (int a = 0; a < 2; a++)
#pragma unroll
            for (int j = 0; j < TNH; j++)
                scratch[((wg * 2 + a) * TNH + j) * 32 + lane] = acc[a][j];
    }
    __syncthreads();
    if (!half) {
#pragma unroll
        for (int a = 0; a < 2; a++)
#pragma unroll
            for (int j = 0; j < TNH; j++)
                acc[a][j] = fadd2(acc[a][j],
                                  scratch[((wg * 2 + a) * TNH + j) * 32 + lane]);
        // bias + CELU, write transposed (2 atoms -> STS.64)
#pragma unroll
        for (int j = 0; j < TNH; j++) {
            float2 b2 = *reinterpret_cast<const float2*>(sB + TN * wg + 2 * j);
            float2 v0 = unpk(acc[0][j]);   // atom0: outputs 2j, 2j+1
            float2 v1 = unpk(acc[1][j]);   // atom1
            float2 o0, o1;
            o0.x = celu_f(v0.x + b2.x);  o0.y = celu_f(v1.x + b2.x);   // row 2j
            o1.x = celu_f(v0.y + b2.y);  o1.y = celu_f(v1.y + b2.y);   // row 2j+1
            *reinterpret_cast<float2*>(sOut + (TN * wg + 2 * j)     * PAD + 2 * lane) = o0;
            *reinterpret_cast<float2*>(sOut + (TN * wg + 2 * j + 1) * PAD + 2 * lane) = o1;
        }
    }
    __syncthreads();
}

__global__ void __launch_bounds__(NT, 1)
k_compute(const float* __restrict__ aev,
          const float* __restrict__ W1, const float* __restrict__ B1,
          const float* __restrict__ W2, const float* __restrict__ B2,
          const float* __restrict__ W3, const float* __restrict__ B3,
          const float* __restrict__ W4, const float* __restrict__ B4,
          float* __restrict__ out) {
    extern __shared__ float sm[];
    float* sA     = sm;                   // D0*PAD (AEV, persists all ensembles)
    float* sHa    = sA  + D0 * PAD;       // D1*PAD (H1, later H3)
    float* sHb    = sHa + D1 * PAD;       // D2*PAD (H2)
    float* sWB    = sHb + D2 * PAD;       // 4*BUFF weight buffers / epilogue scratch
    float* sBias  = sWB + 4 * BUFF;       // D1+D2+D3 floats
    float* sW4b   = sBias + (D1 + D2 + D3);
    float* sAtomE = sW4b + D3;
    int*   sIdx   = reinterpret_cast<int*>(sAtomE + TM);

    const int s    = blockIdx.y;
    const int tid  = threadIdx.x;
    const int lane = tid & 31;
    const int wid  = tid >> 5;
    const int cnt  = g_cnt[s];
    const int base = blockIdx.x * TM;

    if (base < cnt) {
        const int nvalid = min(TM, cnt - base);

        if (tid < TM) {
            int j = min(tid, nvalid - 1);   // padding atoms duplicate a valid one
            sIdx[tid]   = g_idx[s * NMAX + base + j];
            sAtomE[tid] = 0.0f;
        }
        __syncthreads();

        // Gather AEV tile, store transposed [k][atom]
        constexpr int KV = D0 / 4;
        const float4* aev4 = reinterpret_cast<const float4*>(aev);
        for (int l = tid; l < TM * KV; l += NT) {
            int a = l / KV, kq = l % KV;
            float4 v = aev4[(long)sIdx[a] * KV + kq];
            int kb = 4 * kq;
            sA[(kb + 0) * PAD + a] = v.x;
            sA[(kb + 1) * PAD + a] = v.y;
            sA[(kb + 2) * PAD + a] = v.z;
            sA[(kb + 3) * PAD + a] = v.w;
        }
        __syncthreads();

        for (int e = 0; e < E_; e++) {
            const int se = s * E_ + e;

            // stage biases + final-layer weights
            if (tid < D1)                sBias[tid] = B1[se * D1 + tid];
            else if (tid < D1 + D2)      sBias[tid] = B2[se * D2 + tid - D1];
            else if (tid < D1 + D2 + D3) sBias[tid] = B3[se * D3 + tid - D1 - D2];
            if (tid >= NT - D3) sW4b[tid - (NT - D3)] = W4[se * D3 + tid - (NT - D3)];
            __syncthreads();

            gemm_layer<D0, D1, 20>(sA,  W1 + (long)se * D0 * D1, sBias,           sHa,
                                   sWB, tid, lane, wid);
            gemm_layer<D1, D2, 16>(sHa, W2 + (long)se * D1 * D2, sBias + D1,      sHb,
                                   sWB, tid, lane, wid);
            gemm_layer<D2, D3, 12>(sHb, W3 + (long)se * D2 * D3, sBias + D1 + D2, sHa,
                                   sWB, tid, lane, wid);

            // final layer: per-atom dot(h3, w4) + b4; 8 threads per atom
            const float gb4 = B4[se];
            int atom = tid >> 3, q = tid & 7;
            float v = 0.0f;
#pragma unroll
            for (int m = 0; m < 12; m++) {
                int k = q * 12 + m;
                v += sHa[k * PAD + atom] * sW4b[k];
            }
            v += __shfl_xor_sync(0xffffffffu, v, 1);
            v += __shfl_xor_sync(0xffffffffu, v, 2);
            v += __shfl_xor_sync(0xffffffffu, v, 4);
            if (q == 0) sAtomE[atom] += v + gb4;
            __syncthreads();
        }

        // block reduction over valid atoms; mean over E via *0.125
        if (tid < 32) {
            float v = 0.0f;
            if (tid < nvalid)      v += sAtomE[tid];
            if (tid + 32 < nvalid) v += sAtomE[tid + 32];
#pragma unroll
            for (int off = 16; off > 0; off >>= 1)
                v += __shfl_down_sync(0xffffffffu, v, off);
            if (tid == 0) atomicAdd(&g_sum, (double)v * 0.125);
        }
    }

    // every block (including empty tiles) participates in the finish counter
    if (tid == 0) {
        __threadfence();
        int total = gridDim.x * gridDim.y;
        int old = atomicAdd(&g_done, 1);
        if (old == total - 1) {
            double v = atomicAdd(&g_sum, 0.0);   // coherent read
            out[0] = (float)v;
            g_sum  = 0.0;                        // reset for next call
            g_done = 0;
            for (int i = 0; i < S_; i++) g_cnt[i] = 0;
            __threadfence();
        }
    }
}

extern "C" void kernel_launch(void* const* d_in, const int* in_sizes, int n_in,
                              void* d_out, int out_size) {
    const float* aev     = (const float*)d_in[0];
    const int*   species = (const int*)  d_in[1];
    const float* W1 = (const float*)d_in[2];
    const float* B1 = (const float*)d_in[3];
    const float* W2 = (const float*)d_in[4];
    const float* B2 = (const float*)d_in[5];
    const float* W3 = (const float*)d_in[6];
    const float* B3 = (const float*)d_in[7];
    const float* W4 = (const float*)d_in[8];
    const float* B4 = (const float*)d_in[9];
    float* out = (float*)d_out;

    int n = in_sizes[1];
    if (n > NMAX) n = NMAX;

    const size_t smem = (size_t)(D0 + D1 + D2) * PAD * sizeof(float)
                      + (size_t)4 * BUFF * sizeof(float)
                      + (size_t)(D1 + D2 + D3) * sizeof(float)
                      + (size_t)D3 * sizeof(float)
                      + (size_t)TM * sizeof(float)
                      + (size_t)TM * sizeof(int);     // ~226 KB

    cudaFuncSetAttribute(k_compute, cudaFuncAttributeMaxDynamicSharedMemorySize, (int)smem);

    k_bin<<<(n + 511) / 512, 512>>>(species, n);
    const int tiles = (n + TM - 1) / TM;
    k_compute<<<dim3(tiles, S_), NT, smem>>>(aev, W1, B1, W2, B2, W3, B3, W4, B4, out);
}

// round 11
// speedup vs baseline: 1.0005x; 1.0005x over previous
#include <cuda_runtime.h>
#include <math.h>

// ---------------------------------------------------------------------------
// ANI ensemble MLP energy on GB300 (packed fma.rn.f32x2, split-k warp pairs).
// 2-launch cycle: k_bin -> k_compute. Last compute block writes the scalar
// and resets device globals (statics zero-init for call #1).
// Output = sum_a mean_e net_{species[a]}^{(e)}(aev[a]).
// ---------------------------------------------------------------------------

#define NMAX 100000
constexpr int S_ = 4;
constexpr int E_ = 8;
constexpr int D0 = 384, D1 = 160, D2 = 128, D3 = 96;
constexpr int TM = 64;        // atoms per block
constexpr int PAD = 68;       // smem activation row stride (floats)
constexpr int KC = 16;        // K-chunk for weight staging
constexpr int NT = 512;       // 16 warps = 8 output groups x 2 k-halves
constexpr int BUFF = KC * D1; // floats per weight buffer (max-N chunk) = 2560

using u64 = unsigned long long;

__device__ int    g_cnt[S_];      // zero-initialized
__device__ int    g_idx[S_ * NMAX];
__device__ double g_sum;          // zero-initialized
__device__ int    g_done;         // zero-initialized

__global__ void k_bin(const int* __restrict__ species, int n) {
    int i = blockIdx.x * blockDim.x + threadIdx.x;
    int lane = threadIdx.x & 31;
    unsigned active = __ballot_sync(0xffffffffu, i < n);
    if (i < n) {
        int s = species[i] & (S_ - 1);
        unsigned peers = __match_any_sync(active, s);
        int leader = __ffs(peers) - 1;
        int rank = __popc(peers & ((1u << lane) - 1));
        int base = 0;
        if (lane == leader) base = atomicAdd(&g_cnt[s], __popc(peers));
        base = __shfl_sync(peers, base, leader);
        g_idx[s * NMAX + base + rank] = i;
    }
}

__device__ __forceinline__ float celu_f(float x) {
    // jax.nn.celu(x, 0.1) = x>0 ? x : 0.1*expm1(x/0.1)
    return x > 0.0f ? x : 0.1f * expm1f(x * 10.0f);
}

__device__ __forceinline__ u64 splat2(float x) {
    u64 r; asm("mov.b64 %0, {%1, %1};" : "=l"(r) : "f"(x)); return r;
}
__device__ __forceinline__ u64 fma2(u64 a, u64 b, u64 c) {
    u64 d; asm("fma.rn.f32x2 %0, %1, %2, %3;" : "=l"(d) : "l"(a), "l"(b), "l"(c));
    return d;
}
__device__ __forceinline__ u64 fadd2(u64 a, u64 b) {
    u64 d; asm("add.rn.f32x2 %0, %1, %2;" : "=l"(d) : "l"(a), "l"(b));
    return d;
}
__device__ __forceinline__ float2 unpk(u64 a) {
    float2 f; asm("mov.b64 {%0, %1}, %2;" : "=f"(f.x), "=f"(f.y) : "l"(a));
    return f;
}

__device__ __forceinline__ void cp16(float* smem_dst, const float4* gsrc) {
    unsigned a = (unsigned)__cvta_generic_to_shared(smem_dst);
    asm volatile("cp.async.cg.shared.global [%0], [%1], 16;\n" :: "r"(a), "l"(gsrc));
}
__device__ __forceinline__ void cp_commit() {
    asm volatile("cp.async.commit_group;\n");
}

// One dense layer with split-k: sOut[n][atom] = celu(sIn @ gW + sB).
// Warps 0-7 (half=0): output group wg, k in [0, K/2).
// Warps 8-15 (half=1): same output groups, k in [K/2, K).
// acc[atom][j] packs outputs (2j, 2j+1) of group base TN*wg.
// Partials combined through scratch (= the 4 weight buffers) at the epilogue.
template<int K, int N, int TN>
__device__ __forceinline__ void gemm_layer(
    const float* __restrict__ sIn, const float* __restrict__ gW,
    const float* __restrict__ sB, float* __restrict__ sOut,
    float* __restrict__ sWB, int tid, int lane, int wid) {

    constexpr int TNH = TN / 2;
    static_assert((TNH & 1) == 0, "TNH even: float4 weight loads");
    constexpr int C   = K / KC;        // total chunks
    constexpr int H   = C / 2;         // chunks per half
    static_assert(C % 2 == 0, "even chunk count for split-k");
    constexpr int NV4 = KC * N / 4;    // float4 per chunk

    const int half = wid >> 3;         // 0 = lower k, 1 = upper k
    const int wg   = wid & 7;          // output group

    u64 acc[2][TNH];
#pragma unroll
    for (int a = 0; a < 2; a++)
#pragma unroll
        for (int j = 0; j < TNH; j++) acc[a][j] = 0ull;

    const float4* gW4 = reinterpret_cast<const float4*>(gW);
    float* bL[2] = { sWB,            sWB + BUFF     };
    float* bU[2] = { sWB + 2 * BUFF, sWB + 3 * BUFF };

    // prefetch step 0: lower chunk 0 + upper chunk H (one cp.async group)
    for (int l = tid; l < NV4; l += NT) cp16(bL[0] + 4 * l, gW4 + l);
    for (int l = tid; l < NV4; l += NT) cp16(bU[0] + 4 * l, gW4 + (size_t)H * NV4 + l);
    cp_commit();

    int p = 0;
    for (int t = 0; t < H; t++) {
        if (t + 1 < H) {
            const float4* sL = gW4 + (size_t)(t + 1) * NV4;
            const float4* sU = gW4 + (size_t)(H + t + 1) * NV4;
            float* dL = bL[p ^ 1];
            float* dU = bU[p ^ 1];
            for (int l = tid; l < NV4; l += NT) cp16(dL + 4 * l, sL + l);
            for (int l = tid; l < NV4; l += NT) cp16(dU + 4 * l, sU + l);
            cp_commit();
            asm volatile("cp.async.wait_group 1;\n");
        } else {
            asm volatile("cp.async.wait_group 0;\n");
        }
        __syncthreads();

        const float* sW = half ? bU[p] : bL[p];
        const float* inBase = sIn + (half * H + t) * KC * PAD + 2 * lane;
#pragma unroll 4
        for (int kk = 0; kk < KC; kk++) {
            float2 av = *reinterpret_cast<const float2*>(inBase + kk * PAD);
            u64 a0 = splat2(av.x);
            u64 a1 = splat2(av.y);
            const ulonglong2* wr =
                reinterpret_cast<const ulonglong2*>(sW + kk * N + TN * wg);
#pragma unroll
            for (int j2 = 0; j2 < TNH / 2; j2++) {
                ulonglong2 w2 = wr[j2];
                acc[0][2 * j2]     = fma2(a0, w2.x, acc[0][2 * j2]);
                acc[1][2 * j2]     = fma2(a1, w2.x, acc[1][2 * j2]);
                acc[0][2 * j2 + 1] = fma2(a0, w2.y, acc[0][2 * j2 + 1]);
                acc[1][2 * j2 + 1] = fma2(a1, w2.y, acc[1][2 * j2 + 1]);
            }
        }
        __syncthreads();
        p ^= 1;
    }

    // ---- combine halves: upper warps dump partials into scratch (= buffers)
    u64* scratch = reinterpret_cast<u64*>(sWB);   // 8*2*TNH*32 u64 <= 40960 B
    if (half) {
#pragma unroll
        for (int a = 0; a < 2; a++)
#pragma unroll
            for (int j = 0; j < TNH; j++)
                scratch[((wg * 2 + a) * TNH + j) * 32 + lane] = acc[a][j];
    }
    __syncthreads();
    if (!half) {
#pragma unroll
        for (int a = 0; a < 2; a++)
#pragma unroll
            for (int j = 0; j < TNH; j++)
                acc[a][j] = fadd2(acc[a][j],
                                  scratch[((wg * 2 + a) * TNH + j) * 32 + lane]);
        // bias + CELU, write transposed (2 atoms -> STS.64)
#pragma unroll
        for (int j = 0; j < TNH; j++) {
            float2 b2 = *reinterpret_cast<const float2*>(sB + TN * wg + 2 * j);
            float2 v0 = unpk(acc[0][j]);   // atom0: outputs 2j, 2j+1
            float2 v1 = unpk(acc[1][j]);   // atom1
            float2 o0, o1;
            o0.x = celu_f(v0.x + b2.x);  o0.y = celu_f(v1.x + b2.x);   // row 2j
            o1.x = celu_f(v0.y + b2.y);  o1.y = celu_f(v1.y + b2.y);   // row 2j+1
            *reinterpret_cast<float2*>(sOut + (TN * wg + 2 * j)     * PAD + 2 * lane) = o0;
            *reinterpret_cast<float2*>(sOut + (TN * wg + 2 * j + 1) * PAD + 2 * lane) = o1;
        }
    }
    __syncthreads();
}

__global__ void __launch_bounds__(NT, 1)
k_compute(const float* __restrict__ aev,
          const float* __restrict__ W1, const float* __restrict__ B1,
          const float* __restrict__ W2, const float* __restrict__ B2,
          const float* __restrict__ W3, const float* __restrict__ B3,
          const float* __restrict__ W4, const float* __restrict__ B4,
          float* __restrict__ out) {
    extern __shared__ float sm[];
    float* sA     = sm;                   // D0*PAD (AEV, persists all ensembles)
    float* sHa    = sA  + D0 * PAD;       // D1*PAD (H1, later H3)
    float* sHb    = sHa + D1 * PAD;       // D2*PAD (H2)
    float* sWB    = sHb + D2 * PAD;       // 4*BUFF weight buffers / epilogue scratch
    float* sBias  = sWB + 4 * BUFF;       // D1+D2+D3 floats
    float* sW4b   = sBias + (D1 + D2 + D3);
    float* sAtomE = sW4b + D3;
    int*   sIdx   = reinterpret_cast<int*>(sAtomE + TM);

    const int s    = blockIdx.y;
    const int tid  = threadIdx.x;
    const int lane = tid & 31;
    const int wid  = tid >> 5;
    const int cnt  = g_cnt[s];
    const int base = blockIdx.x * TM;

    if (base < cnt) {
        const int nvalid = min(TM, cnt - base);

        if (tid < TM) {
            int j = min(tid, nvalid - 1);   // padding atoms duplicate a valid one
            sIdx[tid]   = g_idx[s * NMAX + base + j];
            sAtomE[tid] = 0.0f;
        }
        __syncthreads();

        // Gather AEV tile, store transposed [k][atom]
        constexpr int KV = D0 / 4;
        const float4* aev4 = reinterpret_cast<const float4*>(aev);
        for (int l = tid; l < TM * KV; l += NT) {
            int a = l / KV, kq = l % KV;
            float4 v = aev4[(long)sIdx[a] * KV + kq];
            int kb = 4 * kq;
            sA[(kb + 0) * PAD + a] = v.x;
            sA[(kb + 1) * PAD + a] = v.y;
            sA[(kb + 2) * PAD + a] = v.z;
            sA[(kb + 3) * PAD + a] = v.w;
        }
        __syncthreads();

        for (int e = 0; e < E_; e++) {
            const int se = s * E_ + e;

            // stage biases + final-layer weights
            if (tid < D1)                sBias[tid] = B1[se * D1 + tid];
            else if (tid < D1 + D2)      sBias[tid] = B2[se * D2 + tid - D1];
            else if (tid < D1 + D2 + D3) sBias[tid] = B3[se * D3 + tid - D1 - D2];
            if (tid >= NT - D3) sW4b[tid - (NT - D3)] = W4[se * D3 + tid - (NT - D3)];
            __syncthreads();

            gemm_layer<D0, D1, 20>(sA,  W1 + (long)se * D0 * D1, sBias,           sHa,
                                   sWB, tid, lane, wid);
            gemm_layer<D1, D2, 16>(sHa, W2 + (long)se * D1 * D2, sBias + D1,      sHb,
                                   sWB, tid, lane, wid);
            gemm_layer<D2, D3, 12>(sHb, W3 + (long)se * D2 * D3, sBias + D1 + D2, sHa,
                                   sWB, tid, lane, wid);

            // final layer: per-atom dot(h3, w4) + b4; 8 threads per atom
            const float gb4 = B4[se];
            int atom = tid >> 3, q = tid & 7;
            float v = 0.0f;
#pragma unroll
            for (int m = 0; m < 12; m++) {
                int k = q * 12 + m;
                v += sHa[k * PAD + atom] * sW4b[k];
            }
            v += __shfl_xor_sync(0xffffffffu, v, 1);
            v += __shfl_xor_sync(0xffffffffu, v, 2);
            v += __shfl_xor_sync(0xffffffffu, v, 4);
            if (q == 0) sAtomE[atom] += v + gb4;
            __syncthreads();
        }

        // block reduction over valid atoms; mean over E via *0.125
        if (tid < 32) {
            float v = 0.0f;
            if (tid < nvalid)      v += sAtomE[tid];
            if (tid + 32 < nvalid) v += sAtomE[tid + 32];
#pragma unroll
            for (int off = 16; off > 0; off >>= 1)
                v += __shfl_down_sync(0xffffffffu, v, off);
            if (tid == 0) atomicAdd(&g_sum, (double)v * 0.125);
        }
    }

    // every block (including empty tiles) participates in the finish counter
    if (tid == 0) {
        __threadfence();
        int total = gridDim.x * gridDim.y;
        int old = atomicAdd(&g_done, 1);
        if (old == total - 1) {
            double v = atomicAdd(&g_sum, 0.0);   // coherent read
            out[0] = (float)v;
            g_sum  = 0.0;                        // reset for next call
            g_done = 0;
            for (int i = 0; i < S_; i++) g_cnt[i] = 0;
            __threadfence();
        }
    }
}

extern "C" void kernel_launch(void* const* d_in, const int* in_sizes, int n_in,
                              void* d_out, int out_size) {
    const float* aev     = (const float*)d_in[0];
    const int*   species = (const int*)  d_in[1];
    const float* W1 = (const float*)d_in[2];
    const float* B1 = (const float*)d_in[3];
    const float* W2 = (const float*)d_in[4];
    const float* B2 = (const float*)d_in[5];
    const float* W3 = (const float*)d_in[6];
    const float* B3 = (const float*)d_in[7];
    const float* W4 = (const float*)d_in[8];
    const float* B4 = (const float*)d_in[9];
    float* out = (float*)d_out;

    int n = in_sizes[1];
    if (n > NMAX) n = NMAX;

    const size_t smem = (size_t)(D0 + D1 + D2) * PAD * sizeof(float)
                      + (size_t)4 * BUFF * sizeof(float)
                      + (size_t)(D1 + D2 + D3) * sizeof(float)
                      + (size_t)D3 * sizeof(float)
                      + (size_t)TM * sizeof(float)
                      + (size_t)TM * sizeof(int);     // ~226 KB

    cudaFuncSetAttribute(k_compute, cudaFuncAttributeMaxDynamicSharedMemorySize, (int)smem);

    k_bin<<<(n + 511) / 512, 512>>>(species, n);
    const int tiles = (n + TM - 1) / TM;
    k_compute<<<dim3(tiles, S_), NT, smem>>>(aev, W1, B1, W2, B2, W3, B3, W4, B4, out);
}

// round 13
// speedup vs baseline: 1.3950x; 1.3943x over previous
#include <cuda_runtime.h>
#include <cuda_bf16.h>
#include <math.h>
#include <stdint.h>

// ---------------------------------------------------------------------------
// ANI ensemble MLP energy on GB300 via mma.sync bf16 (3-pass hi/lo split).
// tcgen05 PTX is rejected (harness targets sm_103 without 'a'); mma.sync
// m16n8k16 bf16 is target-generic and runs on the tensor pipe (HMMA).
// Cycle: k_cvt_w -> k_bin -> k_pad -> k_compute (captured slot 4).
// ---------------------------------------------------------------------------

#define NMAX 100000
constexpr int S_ = 4, E_ = 8;
constexpr int D0 = 384, D1 = 160, D2 = 128, D3 = 96;
constexpr int TM = 64, NT = 256;

// bf16-element pitches (chosen for conflict-free fragment LDS)
constexpr int PA = 392, P1 = 168, P2 = 136, P3 = 104;

// smem byte offsets
constexpr int A_HI = 0;
constexpr int A_LO = A_HI + TM * PA * 2;          //  50176
constexpr int H1_HI = A_LO + TM * PA * 2;         // 100352
constexpr int H1_LO = H1_HI + TM * P1 * 2;        // 121856
constexpr int H2_HI = H1_LO + TM * P1 * 2;        // 143360
constexpr int H2_LO = H2_HI + TM * P2 * 2;        // 160768
constexpr int H3_HI = H1_HI;                      // reuse (H1 dead after L2)
constexpr int H3_LO = H3_HI + TM * P3 * 2;
constexpr int WB0   = H2_LO + TM * P2 * 2;        // 178176
constexpr int WSPL  = 12800;                      // max per-split chunk (N=160 x 40 x 2B)
constexpr int WBUF  = 2 * WSPL;                   // hi+lo per chunk
constexpr int OF_BIAS = WB0 + 2 * WBUF;           // 229376
constexpr int OF_W4   = OF_BIAS + 1536;
constexpr int OF_AE   = OF_W4 + 384;
constexpr int OF_IDX  = OF_AE + 256;
constexpr int SMEMSZ  = OF_IDX + 256;             // 231808 < 232448

// global weight image layout (per net, bytes): [n][k] bf16, hi then lo per layer
constexpr int W1HI = 0,       W1LO = 122880;
constexpr int W2HI = 245760,  W2LO = 286720;
constexpr int W3HI = 327680,  W3LO = 352256;
constexpr int WNET = 376832;

__device__ int g_cnt[S_];
__device__ int g_idx[S_ * NMAX];
__device__ double g_sum;
__device__ int g_done;
__device__ __align__(16) unsigned char g_wimg[32L * WNET];

__device__ __forceinline__ float celu_f(float x) {
    return x > 0.0f ? x : 0.1f * expm1f(x * 10.0f);
}
__device__ __forceinline__ uint32_t pack_hi(float a, float b, float& ra, float& rb) {
    __nv_bfloat16 ha = __float2bfloat16(a), hb = __float2bfloat16(b);
    ra = a - __bfloat162float(ha); rb = b - __bfloat162float(hb);
    return (uint32_t)__bfloat16_as_ushort(ha) | ((uint32_t)__bfloat16_as_ushort(hb) << 16);
}
__device__ __forceinline__ uint32_t pack_bf(float a, float b) {
    return (uint32_t)__bfloat16_as_ushort(__float2bfloat16(a))
         | ((uint32_t)__bfloat16_as_ushort(__float2bfloat16(b)) << 16);
}
__device__ __forceinline__ void cp16(char* d, const void* s) {
    asm volatile("cp.async.cg.shared.global [%0], [%1], 16;\n"
        :: "r"((uint32_t)__cvta_generic_to_shared(d)), "l"(s));
}
__device__ __forceinline__ void mma4(float* c, uint32_t a0, uint32_t a1, uint32_t a2,
                                     uint32_t a3, uint32_t b0, uint32_t b1) {
    asm volatile("mma.sync.aligned.m16n8k16.row.col.f32.bf16.bf16.f32 "
        "{%0,%1,%2,%3},{%4,%5,%6,%7},{%8,%9},{%0,%1,%2,%3};"
        : "+f"(c[0]), "+f"(c[1]), "+f"(c[2]), "+f"(c[3])
        : "r"(a0), "r"(a1), "r"(a2), "r"(a3), "r"(b0), "r"(b1));
}

__global__ void k_cvt_w(const float* __restrict__ W1, const float* __restrict__ W2,
                        const float* __restrict__ W3) {
    int se = blockIdx.x, tid = threadIdx.x;
    unsigned char* nb = g_wimg + (long)se * WNET;
    for (int i = tid; i < (D0 / 2) * D1; i += NT) {
        int n = i % D1, k = 2 * (i / D1);
        float r0, r1;
        uint32_t h = pack_hi(W1[((long)se * D0 + k) * D1 + n],
                             W1[((long)se * D0 + k + 1) * D1 + n], r0, r1);
        uint32_t o = (uint32_t)(n * D0 + k) * 2;
        *(uint32_t*)(nb + W1HI + o) = h;
        *(uint32_t*)(nb + W1LO + o) = pack_bf(r0, r1);
    }
    for (int i = tid; i < (D1 / 2) * D2; i += NT) {
        int n = i % D2, k = 2 * (i / D2);
        float r0, r1;
        uint32_t h = pack_hi(W2[((long)se * D1 + k) * D2 + n],
                             W2[((long)se * D1 + k + 1) * D2 + n], r0, r1);
        uint32_t o = (uint32_t)(n * D1 + k) * 2;
        *(uint32_t*)(nb + W2HI + o) = h;
        *(uint32_t*)(nb + W2LO + o) = pack_bf(r0, r1);
    }
    for (int i = tid; i < (D2 / 2) * D3; i += NT) {
        int n = i % D3, k = 2 * (i / D3);
        float r0, r1;
        uint32_t h = pack_hi(W3[((long)se * D2 + k) * D3 + n],
                             W3[((long)se * D2 + k + 1) * D3 + n], r0, r1);
        uint32_t o = (uint32_t)(n * D2 + k) * 2;
        *(uint32_t*)(nb + W3HI + o) = h;
        *(uint32_t*)(nb + W3LO + o) = pack_bf(r0, r1);
    }
}

__global__ void k_bin(const int* __restrict__ species, int n) {
    int i = blockIdx.x * blockDim.x + threadIdx.x;
    int lane = threadIdx.x & 31;
    unsigned active = __ballot_sync(0xffffffffu, i < n);
    if (i < n) {
        int s = species[i] & (S_ - 1);
        unsigned peers = __match_any_sync(active, s);
        int leader = __ffs(peers) - 1;
        int rank = __popc(peers & ((1u << lane) - 1));
        int b = 0;
        if (lane == leader) b = atomicAdd(&g_cnt[s], __popc(peers));
        b = __shfl_sync(peers, b, leader);
        g_idx[s * NMAX + b + rank] = i;
    }
}

__global__ void k_pad() {}

// Stage one K32 weight chunk (hi+lo) into buf: [n][40 elems] per split.
template<int K, int N>
__device__ __forceinline__ void stage(char* buf, const unsigned char* gHi,
                                      const unsigned char* gLo, int c, int tid) {
    for (int i = tid; i < N * 4; i += NT) {
        int n = i >> 2, h = (i & 3) << 4;
        cp16(buf + n * 80 + h,        gHi + (long)n * K * 2 + c * 64 + h);
        cp16(buf + WSPL + n * 80 + h, gLo + (long)n * K * 2 + c * 64 + h);
    }
    asm volatile("cp.async.commit_group;\n");
}

// One layer: out[m][n] = celu(in[m][:K] @ W[K][N] + bias).
// Warps: (wid&3) = m-strip of 16, (wid>>2) = n-half. 3-pass bf16 split MMA.
template<int K, int N, int PIN, int POUT>
__device__ __forceinline__ void mma_layer(char* sm, int aHi, int aLo,
        const unsigned char* gHi, const unsigned char* gLo,
        int oHi, int oLo, const float* __restrict__ bias,
        int tid, int lane, int wid) {
    constexpr int ST = K / 16, CH = ST / 2, NTL = N / 16;
    const int m0 = (wid & 3) << 4, ng = wid >> 2;
    const int r = lane >> 2, cq = (lane & 3) * 2;

    float acc[NTL][4];
#pragma unroll
    for (int t = 0; t < NTL; t++)
#pragma unroll
        for (int j = 0; j < 4; j++) acc[t][j] = 0.f;

    char* wb[2] = { sm + WB0, sm + WB0 + WBUF };
    stage<K, N>(wb[0], gHi, gLo, 0, tid);
    int p = 0;
    for (int c = 0; c < CH; c++) {
        if (c + 1 < CH) {
            stage<K, N>(wb[p ^ 1], gHi, gLo, c + 1, tid);
            asm volatile("cp.async.wait_group 1;\n");
        } else {
            asm volatile("cp.async.wait_group 0;\n");
        }
        __syncthreads();
        char* bufH = wb[p];
        char* bufL = bufH + WSPL;
#pragma unroll
        for (int sh = 0; sh < 2; sh++) {
            int k0 = (2 * c + sh) * 16;
            int abase = ((m0 + r) * PIN + k0 + cq) * 2;
            uint32_t ah0 = *(uint32_t*)(sm + aHi + abase);
            uint32_t ah1 = *(uint32_t*)(sm + aHi + abase + 8 * PIN * 2);
            uint32_t ah2 = *(uint32_t*)(sm + aHi + abase + 16);
            uint32_t ah3 = *(uint32_t*)(sm + aHi + abase + 8 * PIN * 2 + 16);
            uint32_t al0 = *(uint32_t*)(sm + aLo + abase);
            uint32_t al1 = *(uint32_t*)(sm + aLo + abase + 8 * PIN * 2);
            uint32_t al2 = *(uint32_t*)(sm + aLo + abase + 16);
            uint32_t al3 = *(uint32_t*)(sm + aLo + abase + 8 * PIN * 2 + 16);
#pragma unroll
            for (int nt = 0; nt < NTL; nt++) {
                int nb = (ng * (N / 2) + nt * 8 + r) * 80 + (sh * 16 + cq) * 2;
                uint32_t bh0 = *(uint32_t*)(bufH + nb);
                uint32_t bh1 = *(uint32_t*)(bufH + nb + 16);
                uint32_t bl0 = *(uint32_t*)(bufL + nb);
                uint32_t bl1 = *(uint32_t*)(bufL + nb + 16);
                mma4(acc[nt], ah0, ah1, ah2, ah3, bh0, bh1);
                mma4(acc[nt], al0, al1, al2, al3, bh0, bh1);
                mma4(acc[nt], ah0, ah1, ah2, ah3, bl0, bl1);
            }
        }
        __syncthreads();
        p ^= 1;
    }
    // epilogue: bias + CELU -> split hi/lo -> next A-image
#pragma unroll
    for (int nt = 0; nt < NTL; nt++) {
        int col = ng * (N / 2) + nt * 8 + cq;
        float b0 = bias[col], b1 = bias[col + 1];
        float h00 = celu_f(acc[nt][0] + b0), h01 = celu_f(acc[nt][1] + b1);
        float h10 = celu_f(acc[nt][2] + b0), h11 = celu_f(acc[nt][3] + b1);
        float r0, r1;
        uint32_t w0 = pack_hi(h00, h01, r0, r1);
        uint32_t w0l = pack_bf(r0, r1);
        uint32_t w1 = pack_hi(h10, h11, r0, r1);
        uint32_t w1l = pack_bf(r0, r1);
        int o0 = ((m0 + r) * POUT + col) * 2, o1 = ((m0 + r + 8) * POUT + col) * 2;
        *(uint32_t*)(sm + oHi + o0) = w0;  *(uint32_t*)(sm + oLo + o0) = w0l;
        *(uint32_t*)(sm + oHi + o1) = w1;  *(uint32_t*)(sm + oLo + o1) = w1l;
    }
    __syncthreads();
}

__global__ void __launch_bounds__(NT, 1)
k_compute(const float* __restrict__ aev,
          const float* __restrict__ B1, const float* __restrict__ B2,
          const float* __restrict__ B3, const float* __restrict__ W4,
          const float* __restrict__ B4, float* __restrict__ out) {
    extern __shared__ char sm[];
    const int s = blockIdx.y, tx = blockIdx.x, tid = threadIdx.x;
    const int lane = tid & 31, wid = tid >> 5;
    const int cnt = g_cnt[s], base = tx * TM;
    float* sBias  = (float*)(sm + OF_BIAS);
    float* sW4    = (float*)(sm + OF_W4);
    float* sAtomE = (float*)(sm + OF_AE);
    int*   sIdx   = (int*)(sm + OF_IDX);

    if (base < cnt) {
        const int nvalid = min(TM, cnt - base);
        if (tid < TM) {
            sIdx[tid] = g_idx[s * NMAX + base + min(tid, nvalid - 1)];
            sAtomE[tid] = 0.f;
        }
        __syncthreads();
        // AEV -> bf16 hi/lo A-image (once per tile, reused by all ensembles)
        for (int i = tid; i < TM * (D0 / 2); i += NT) {
            int rr = i / (D0 / 2), k = 2 * (i % (D0 / 2));
            float2 v = *(const float2*)(aev + (long)sIdx[rr] * D0 + k);
            float r0, r1;
            uint32_t h = pack_hi(v.x, v.y, r0, r1);
            int o = (rr * PA + k) * 2;
            *(uint32_t*)(sm + A_HI + o) = h;
            *(uint32_t*)(sm + A_LO + o) = pack_bf(r0, r1);
        }
        __syncthreads();

        const unsigned char* wn0 = g_wimg + (long)(s * E_) * WNET;
        for (int e = 0; e < E_; e++) {
            const unsigned char* wn = wn0 + (long)e * WNET;
            const int se = s * E_ + e;
            for (int t = tid; t < 480; t += NT) {
                if (t < D1)       sBias[t] = B1[se * D1 + t];
                else if (t < 288) sBias[t] = B2[se * D2 + t - D1];
                else if (t < 384) sBias[t] = B3[se * D3 + t - 288];
                else              sW4[t - 384] = W4[se * D3 + t - 384];
            }
            __syncthreads();

            mma_layer<D0, D1, PA, P1>(sm, A_HI, A_LO, wn + W1HI, wn + W1LO,
                                      H1_HI, H1_LO, sBias, tid, lane, wid);
            mma_layer<D1, D2, P1, P2>(sm, H1_HI, H1_LO, wn + W2HI, wn + W2LO,
                                      H2_HI, H2_LO, sBias + D1, tid, lane, wid);
            mma_layer<D2, D3, P2, P3>(sm, H2_HI, H2_LO, wn + W3HI, wn + W3LO,
                                      H3_HI, H3_LO, sBias + 288, tid, lane, wid);

            // layer 4: per-atom dot(h3, w4); 4 threads per atom (same warp)
            {
                int atom = tid >> 2, q = tid & 3;
                float v = 0.f;
#pragma unroll
                for (int m = 0; m < 24; m += 2) {
                    int k = q * 24 + m;
                    uint32_t hw = *(uint32_t*)(sm + H3_HI + (atom * P3 + k) * 2);
                    uint32_t lw = *(uint32_t*)(sm + H3_LO + (atom * P3 + k) * 2);
                    float x0 = __bfloat162float(__ushort_as_bfloat16((unsigned short)(hw & 0xffff)))
                             + __bfloat162float(__ushort_as_bfloat16((unsigned short)(lw & 0xffff)));
                    float x1 = __bfloat162float(__ushort_as_bfloat16((unsigned short)(hw >> 16)))
                             + __bfloat162float(__ushort_as_bfloat16((unsigned short)(lw >> 16)));
                    v += x0 * sW4[k] + x1 * sW4[k + 1];
                }
                v += __shfl_xor_sync(0xffffffffu, v, 1);
                v += __shfl_xor_sync(0xffffffffu, v, 2);
                if (q == 0) sAtomE[atom] += v;
                __syncthreads();
            }
        }

        // reduce valid atoms; + sum of b4 per atom; mean over E
        if (tid < 32) {
            float sb4 = 0.f;
            for (int e = 0; e < E_; e++) sb4 += __ldg(B4 + s * E_ + e);
            float v = 0.f;
            for (int t = tid; t < nvalid; t += 32) v += sAtomE[t] + sb4;
#pragma unroll
            for (int o = 16; o > 0; o >>= 1) v += __shfl_down_sync(0xffffffffu, v, o);
            if (tid == 0) atomicAdd(&g_sum, (double)v * 0.125);
        }
    }

    if (tid == 0) {
        __threadfence();
        int total = gridDim.x * gridDim.y;
        if (atomicAdd(&g_done, 1) == total - 1) {
            double v = atomicAdd(&g_sum, 0.0);
            out[0] = (float)v;
            g_sum = 0.0;
            g_done = 0;
            for (int i = 0; i < S_; i++) g_cnt[i] = 0;
            __threadfence();
        }
    }
}

extern "C" void kernel_launch(void* const* d_in, const int* in_sizes, int n_in,
                              void* d_out, int out_size) {
    const float* aev     = (const float*)d_in[0];
    const int*   species = (const int*)  d_in[1];
    const float* W1 = (const float*)d_in[2];
    const float* B1 = (const float*)d_in[3];
    const float* W2 = (const float*)d_in[4];
    const float* B2 = (const float*)d_in[5];
    const float* W3 = (const float*)d_in[6];
    const float* B3 = (const float*)d_in[7];
    const float* W4 = (const float*)d_in[8];
    const float* B4 = (const float*)d_in[9];
    float* out = (float*)d_out;

    int n = in_sizes[1];
    if (n > NMAX) n = NMAX;

    cudaFuncSetAttribute(k_compute, cudaFuncAttributeMaxDynamicSharedMemorySize, SMEMSZ);

    k_cvt_w<<<32, NT>>>(W1, W2, W3);
    k_bin<<<(n + 511) / 512, 512>>>(species, n);
    k_pad<<<1, 32>>>();
    const int tiles = (n + TM - 1) / TM;
    k_compute<<<dim3(tiles, S_), NT, SMEMSZ>>>(aev, B1, B2, B3, W4, B4, out);
}

// round 14
// speedup vs baseline: 1.5797x; 1.1324x over previous
#include <cuda_runtime.h>
#include <cuda_bf16.h>
#include <math.h>
#include <stdint.h>

// ---------------------------------------------------------------------------
// ANI ensemble MLP energy on GB300 via mma.sync bf16 (3-pass hi/lo split).
// R14: 512 threads (4 m-strips x 4 n-groups) for 2x warp parallelism.
// Cycle: k_cvt_w -> k_bin -> k_pad -> k_compute (captured slot 4).
// ---------------------------------------------------------------------------

#define NMAX 100000
constexpr int S_ = 4, E_ = 8;
constexpr int D0 = 384, D1 = 160, D2 = 128, D3 = 96;
constexpr int TM = 64, NT = 512;

// bf16-element pitches (conflict-free fragment LDS; pitch/2 mod 32 coprime sets)
constexpr int PA = 392, P1 = 168, P2 = 136, P3 = 104;

// smem byte offsets
constexpr int A_HI = 0;
constexpr int A_LO = A_HI + TM * PA * 2;          //  50176
constexpr int H1_HI = A_LO + TM * PA * 2;         // 100352
constexpr int H1_LO = H1_HI + TM * P1 * 2;        // 121856
constexpr int H2_HI = H1_LO + TM * P1 * 2;        // 143360
constexpr int H2_LO = H2_HI + TM * P2 * 2;        // 160768
constexpr int H3_HI = H1_HI;                      // reuse (H1 dead after L2)
constexpr int H3_LO = H3_HI + TM * P3 * 2;
constexpr int WB0   = H2_LO + TM * P2 * 2;        // 178176
constexpr int WSPL  = 12800;                      // max per-split chunk (N=160 x 40 x 2B)
constexpr int WBUF  = 2 * WSPL;
constexpr int OF_BIAS = WB0 + 2 * WBUF;           // 229376
constexpr int OF_W4   = OF_BIAS + 1536;
constexpr int OF_AE   = OF_W4 + 384;
constexpr int OF_IDX  = OF_AE + 256;
constexpr int SMEMSZ  = OF_IDX + 256;             // 231808 < 232448

// global weight image layout (per net, bytes): [n][k] bf16, hi then lo per layer
constexpr int W1HI = 0,       W1LO = 122880;
constexpr int W2HI = 245760,  W2LO = 286720;
constexpr int W3HI = 327680,  W3LO = 352256;
constexpr int WNET = 376832;

__device__ int g_cnt[S_];
__device__ int g_idx[S_ * NMAX];
__device__ double g_sum;
__device__ int g_done;
__device__ __align__(16) unsigned char g_wimg[32L * WNET];

__device__ __forceinline__ float celu_f(float x) {
    return x > 0.0f ? x : 0.1f * expm1f(x * 10.0f);
}
__device__ __forceinline__ uint32_t pack_hi(float a, float b, float& ra, float& rb) {
    __nv_bfloat16 ha = __float2bfloat16(a), hb = __float2bfloat16(b);
    ra = a - __bfloat162float(ha); rb = b - __bfloat162float(hb);
    return (uint32_t)__bfloat16_as_ushort(ha) | ((uint32_t)__bfloat16_as_ushort(hb) << 16);
}
__device__ __forceinline__ uint32_t pack_bf(float a, float b) {
    return (uint32_t)__bfloat16_as_ushort(__float2bfloat16(a))
         | ((uint32_t)__bfloat16_as_ushort(__float2bfloat16(b)) << 16);
}
__device__ __forceinline__ void cp16(char* d, const void* s) {
    asm volatile("cp.async.cg.shared.global [%0], [%1], 16;\n"
        :: "r"((uint32_t)__cvta_generic_to_shared(d)), "l"(s));
}
__device__ __forceinline__ void mma4(float* c, uint32_t a0, uint32_t a1, uint32_t a2,
                                     uint32_t a3, uint32_t b0, uint32_t b1) {
    asm volatile("mma.sync.aligned.m16n8k16.row.col.f32.bf16.bf16.f32 "
        "{%0,%1,%2,%3},{%4,%5,%6,%7},{%8,%9},{%0,%1,%2,%3};"
        : "+f"(c[0]), "+f"(c[1]), "+f"(c[2]), "+f"(c[3])
        : "r"(a0), "r"(a1), "r"(a2), "r"(a3), "r"(b0), "r"(b1));
}

__global__ void k_cvt_w(const float* __restrict__ W1, const float* __restrict__ W2,
                        const float* __restrict__ W3) {
    int se = blockIdx.x, tid = threadIdx.x;
    unsigned char* nb = g_wimg + (long)se * WNET;
    for (int i = tid; i < (D0 / 2) * D1; i += 256) {
        int n = i % D1, k = 2 * (i / D1);
        float r0, r1;
        uint32_t h = pack_hi(W1[((long)se * D0 + k) * D1 + n],
                             W1[((long)se * D0 + k + 1) * D1 + n], r0, r1);
        uint32_t o = (uint32_t)(n * D0 + k) * 2;
        *(uint32_t*)(nb + W1HI + o) = h;
        *(uint32_t*)(nb + W1LO + o) = pack_bf(r0, r1);
    }
    for (int i = tid; i < (D1 / 2) * D2; i += 256) {
        int n = i % D2, k = 2 * (i / D2);
        float r0, r1;
        uint32_t h = pack_hi(W2[((long)se * D1 + k) * D2 + n],
                             W2[((long)se * D1 + k + 1) * D2 + n], r0, r1);
        uint32_t o = (uint32_t)(n * D1 + k) * 2;
        *(uint32_t*)(nb + W2HI + o) = h;
        *(uint32_t*)(nb + W2LO + o) = pack_bf(r0, r1);
    }
    for (int i = tid; i < (D2 / 2) * D3; i += 256) {
        int n = i % D3, k = 2 * (i / D3);
        float r0, r1;
        uint32_t h = pack_hi(W3[((long)se * D2 + k) * D3 + n],
                             W3[((long)se * D2 + k + 1) * D3 + n], r0, r1);
        uint32_t o = (uint32_t)(n * D2 + k) * 2;
        *(uint32_t*)(nb + W3HI + o) = h;
        *(uint32_t*)(nb + W3LO + o) = pack_bf(r0, r1);
    }
}

__global__ void k_bin(const int* __restrict__ species, int n) {
    int i = blockIdx.x * blockDim.x + threadIdx.x;
    int lane = threadIdx.x & 31;
    unsigned active = __ballot_sync(0xffffffffu, i < n);
    if (i < n) {
        int s = species[i] & (S_ - 1);
        unsigned peers = __match_any_sync(active, s);
        int leader = __ffs(peers) - 1;
        int rank = __popc(peers & ((1u << lane) - 1));
        int b = 0;
        if (lane == leader) b = atomicAdd(&g_cnt[s], __popc(peers));
        b = __shfl_sync(peers, b, leader);
        g_idx[s * NMAX + b + rank] = i;
    }
}

__global__ void k_pad() {}

// Stage one K32 weight chunk (hi+lo) into buf: [n][40 elems] per split.
template<int K, int N>
__device__ __forceinline__ void stage(char* buf, const unsigned char* gHi,
                                      const unsigned char* gLo, int c, int tid) {
    for (int i = tid; i < N * 4; i += NT) {
        int n = i >> 2, h = (i & 3) << 4;
        cp16(buf + n * 80 + h,        gHi + (long)n * K * 2 + c * 64 + h);
        cp16(buf + WSPL + n * 80 + h, gLo + (long)n * K * 2 + c * 64 + h);
    }
    asm volatile("cp.async.commit_group;\n");
}

// One layer: out[m][n] = celu(in[m][:K] @ W[K][N] + bias).
// 16 warps: (wid&3) = m-strip of 16, (wid>>2) = n-quarter. 3-pass split MMA.
template<int K, int N, int PIN, int POUT>
__device__ __forceinline__ void mma_layer(char* sm, int aHi, int aLo,
        const unsigned char* gHi, const unsigned char* gLo,
        int oHi, int oLo, const float* __restrict__ bias,
        int tid, int lane, int wid) {
    constexpr int CH = K / 32, NTL = N / 32;   // chunks, n8-tiles per n-quarter
    const int m0 = (wid & 3) << 4, ng = wid >> 2;
    const int r = lane >> 2, cq = (lane & 3) * 2;

    float acc[NTL][4];
#pragma unroll
    for (int t = 0; t < NTL; t++)
#pragma unroll
        for (int j = 0; j < 4; j++) acc[t][j] = 0.f;

    char* wb[2] = { sm + WB0, sm + WB0 + WBUF };
    stage<K, N>(wb[0], gHi, gLo, 0, tid);
    int p = 0;
    for (int c = 0; c < CH; c++) {
        if (c + 1 < CH) {
            stage<K, N>(wb[p ^ 1], gHi, gLo, c + 1, tid);
            asm volatile("cp.async.wait_group 1;\n");
        } else {
            asm volatile("cp.async.wait_group 0;\n");
        }
        __syncthreads();
        char* bufH = wb[p];
        char* bufL = bufH + WSPL;
#pragma unroll
        for (int sh = 0; sh < 2; sh++) {
            int k0 = (2 * c + sh) * 16;
            int abase = ((m0 + r) * PIN + k0 + cq) * 2;
            uint32_t ah0 = *(uint32_t*)(sm + aHi + abase);
            uint32_t ah1 = *(uint32_t*)(sm + aHi + abase + 8 * PIN * 2);
            uint32_t ah2 = *(uint32_t*)(sm + aHi + abase + 16);
            uint32_t ah3 = *(uint32_t*)(sm + aHi + abase + 8 * PIN * 2 + 16);
            uint32_t al0 = *(uint32_t*)(sm + aLo + abase);
            uint32_t al1 = *(uint32_t*)(sm + aLo + abase + 8 * PIN * 2);
            uint32_t al2 = *(uint32_t*)(sm + aLo + abase + 16);
            uint32_t al3 = *(uint32_t*)(sm + aLo + abase + 8 * PIN * 2 + 16);
#pragma unroll
            for (int nt = 0; nt < NTL; nt++) {
                int nb = (ng * (N / 4) + nt * 8 + r) * 80 + (sh * 16 + cq) * 2;
                uint32_t bh0 = *(uint32_t*)(bufH + nb);
                uint32_t bh1 = *(uint32_t*)(bufH + nb + 16);
                uint32_t bl0 = *(uint32_t*)(bufL + nb);
                uint32_t bl1 = *(uint32_t*)(bufL + nb + 16);
                mma4(acc[nt], ah0, ah1, ah2, ah3, bh0, bh1);
                mma4(acc[nt], al0, al1, al2, al3, bh0, bh1);
                mma4(acc[nt], ah0, ah1, ah2, ah3, bl0, bl1);
            }
        }
        __syncthreads();
        p ^= 1;
    }
    // epilogue: bias + CELU -> split hi/lo -> next A-image
#pragma unroll
    for (int nt = 0; nt < NTL; nt++) {
        int col = ng * (N / 4) + nt * 8 + cq;
        float b0 = bias[col], b1 = bias[col + 1];
        float h00 = celu_f(acc[nt][0] + b0), h01 = celu_f(acc[nt][1] + b1);
        float h10 = celu_f(acc[nt][2] + b0), h11 = celu_f(acc[nt][3] + b1);
        float r0, r1;
        uint32_t w0 = pack_hi(h00, h01, r0, r1);
        uint32_t w0l = pack_bf(r0, r1);
        uint32_t w1 = pack_hi(h10, h11, r0, r1);
        uint32_t w1l = pack_bf(r0, r1);
        int o0 = ((m0 + r) * POUT + col) * 2, o1 = ((m0 + r + 8) * POUT + col) * 2;
        *(uint32_t*)(sm + oHi + o0) = w0;  *(uint32_t*)(sm + oLo + o0) = w0l;
        *(uint32_t*)(sm + oHi + o1) = w1;  *(uint32_t*)(sm + oLo + o1) = w1l;
    }
    __syncthreads();
}

__global__ void __launch_bounds__(NT, 1)
k_compute(const float* __restrict__ aev,
          const float* __restrict__ B1, const float* __restrict__ B2,
          const float* __restrict__ B3, const float* __restrict__ W4,
          const float* __restrict__ B4, float* __restrict__ out) {
    extern __shared__ char sm[];
    const int s = blockIdx.y, tx = blockIdx.x, tid = threadIdx.x;
    const int lane = tid & 31, wid = tid >> 5;
    const int cnt = g_cnt[s], base = tx * TM;
    float* sBias  = (float*)(sm + OF_BIAS);
    float* sW4    = (float*)(sm + OF_W4);
    float* sAtomE = (float*)(sm + OF_AE);
    int*   sIdx   = (int*)(sm + OF_IDX);

    if (base < cnt) {
        const int nvalid = min(TM, cnt - base);
        if (tid < TM) {
            sIdx[tid] = g_idx[s * NMAX + base + min(tid, nvalid - 1)];
            sAtomE[tid] = 0.f;
        }
        __syncthreads();
        // AEV -> bf16 hi/lo A-image (once per tile, reused by all ensembles)
        for (int i = tid; i < TM * (D0 / 2); i += NT) {
            int rr = i / (D0 / 2), k = 2 * (i % (D0 / 2));
            float2 v = *(const float2*)(aev + (long)sIdx[rr] * D0 + k);
            float r0, r1;
            uint32_t h = pack_hi(v.x, v.y, r0, r1);
            int o = (rr * PA + k) * 2;
            *(uint32_t*)(sm + A_HI + o) = h;
            *(uint32_t*)(sm + A_LO + o) = pack_bf(r0, r1);
        }
        __syncthreads();

        const unsigned char* wn0 = g_wimg + (long)(s * E_) * WNET;
        for (int e = 0; e < E_; e++) {
            const unsigned char* wn = wn0 + (long)e * WNET;
            const int se = s * E_ + e;
            for (int t = tid; t < 480; t += NT) {
                if (t < D1)       sBias[t] = B1[se * D1 + t];
                else if (t < 288) sBias[t] = B2[se * D2 + t - D1];
                else if (t < 384) sBias[t] = B3[se * D3 + t - 288];
                else              sW4[t - 384] = W4[se * D3 + t - 384];
            }
            __syncthreads();

            mma_layer<D0, D1, PA, P1>(sm, A_HI, A_LO, wn + W1HI, wn + W1LO,
                                      H1_HI, H1_LO, sBias, tid, lane, wid);
            mma_layer<D1, D2, P1, P2>(sm, H1_HI, H1_LO, wn + W2HI, wn + W2LO,
                                      H2_HI, H2_LO, sBias + D1, tid, lane, wid);
            mma_layer<D2, D3, P2, P3>(sm, H2_HI, H2_LO, wn + W3HI, wn + W3LO,
                                      H3_HI, H3_LO, sBias + 288, tid, lane, wid);

            // layer 4: per-atom dot(h3, w4); 8 threads per atom
            {
                int atom = tid >> 3, q = tid & 7;
                float v = 0.f;
#pragma unroll
                for (int m = 0; m < 12; m += 2) {
                    int k = q * 12 + m;
                    uint32_t hw = *(uint32_t*)(sm + H3_HI + (atom * P3 + k) * 2);
                    uint32_t lw = *(uint32_t*)(sm + H3_LO + (atom * P3 + k) * 2);
                    float x0 = __bfloat162float(__ushort_as_bfloat16((unsigned short)(hw & 0xffff)))
                             + __bfloat162float(__ushort_as_bfloat16((unsigned short)(lw & 0xffff)));
                    float x1 = __bfloat162float(__ushort_as_bfloat16((unsigned short)(hw >> 16)))
                             + __bfloat162float(__ushort_as_bfloat16((unsigned short)(lw >> 16)));
                    v += x0 * sW4[k] + x1 * sW4[k + 1];
                }
                v += __shfl_xor_sync(0xffffffffu, v, 1);
                v += __shfl_xor_sync(0xffffffffu, v, 2);
                v += __shfl_xor_sync(0xffffffffu, v, 4);
                if (q == 0) sAtomE[atom] += v;
                __syncthreads();
            }
        }

        // reduce valid atoms; + sum of b4 per atom; mean over E
        if (tid < 32) {
            float sb4 = 0.f;
            for (int e = 0; e < E_; e++) sb4 += __ldg(B4 + s * E_ + e);
            float v = 0.f;
            for (int t = tid; t < nvalid; t += 32) v += sAtomE[t] + sb4;
#pragma unroll
            for (int o = 16; o > 0; o >>= 1) v += __shfl_down_sync(0xffffffffu, v, o);
            if (tid == 0) atomicAdd(&g_sum, (double)v * 0.125);
        }
    }

    if (tid == 0) {
        __threadfence();
        int total = gridDim.x * gridDim.y;
        if (atomicAdd(&g_done, 1) == total - 1) {
            double v = atomicAdd(&g_sum, 0.0);
            out[0] = (float)v;
            g_sum = 0.0;
            g_done = 0;
            for (int i = 0; i < S_; i++) g_cnt[i] = 0;
            __threadfence();
        }
    }
}

extern "C" void kernel_launch(void* const* d_in, const int* in_sizes, int n_in,
                              void* d_out, int out_size) {
    const float* aev     = (const float*)d_in[0];
    const int*   species = (const int*)  d_in[1];
    const float* W1 = (const float*)d_in[2];
    const float* B1 = (const float*)d_in[3];
    const float* W2 = (const float*)d_in[4];
    const float* B2 = (const float*)d_in[5];
    const float* W3 = (const float*)d_in[6];
    const float* B3 = (const float*)d_in[7];
    const float* W4 = (const float*)d_in[8];
    const float* B4 = (const float*)d_in[9];
    float* out = (float*)d_out;

    int n = in_sizes[1];
    if (n > NMAX) n = NMAX;

    cudaFuncSetAttribute(k_compute, cudaFuncAttributeMaxDynamicSharedMemorySize, SMEMSZ);

    k_cvt_w<<<32, 256>>>(W1, W2, W3);
    k_bin<<<(n + 511) / 512, 512>>>(species, n);
    k_pad<<<1, 32>>>();
    const int tiles = (n + TM - 1) / TM;
    k_compute<<<dim3(tiles, S_), NT, SMEMSZ>>>(aev, B1, B2, B3, W4, B4, out);
}

// round 17
// speedup vs baseline: 1.9568x; 1.2387x over previous
#include <cuda_runtime.h>
#include <cuda_bf16.h>
#include <math.h>
#include <stdint.h>

// ---------------------------------------------------------------------------
// ANI ensemble MLP energy on GB300 via mma.sync bf16 (3-pass hi/lo split).
// R16 = R15 resubmit (R15 failed on harness device-init infra flake, not
// kernel): ldmatrix fragment loads, single-sync chunks, chained chunk-0
// prefetch, exact 1-D work-list grid.
// Cycle: k_cvt_w -> k_bin -> k_pad -> k_compute (captured slot 4).
// ---------------------------------------------------------------------------

#define NMAX 100000
constexpr int S_ = 4, E_ = 8;
constexpr int D0 = 384, D1 = 160, D2 = 128, D3 = 96;
constexpr int TM = 64, NT = 512;

// bf16-element pitches (conflict-free for both LDS.32 and ldmatrix row reads)
constexpr int PA = 392, P1 = 168, P2 = 136, P3 = 104;

// smem byte offsets
constexpr int A_HI = 0;
constexpr int A_LO = A_HI + TM * PA * 2;          //  50176
constexpr int H1_HI = A_LO + TM * PA * 2;         // 100352
constexpr int H1_LO = H1_HI + TM * P1 * 2;        // 121856
constexpr int H2_HI = H1_LO + TM * P1 * 2;        // 143360
constexpr int H2_LO = H2_HI + TM * P2 * 2;        // 160768
constexpr int H3_HI = H1_HI;                      // reuse (H1 dead after L2)
constexpr int H3_LO = H3_HI + TM * P3 * 2;
constexpr int WB0   = H2_LO + TM * P2 * 2;        // 178176
constexpr int WSPL  = 12800;                      // max per-split chunk
constexpr int WBUF  = 2 * WSPL;
constexpr int OF_BIAS = WB0 + 2 * WBUF;           // 229376
constexpr int OF_W4   = OF_BIAS + 1536;
constexpr int OF_AE   = OF_W4 + 384;
constexpr int OF_IDX  = OF_AE + 256;
constexpr int SMEMSZ  = OF_IDX + 256;             // 231808 < 232448

// global weight image (per net, bytes): [n][k] bf16, hi then lo per layer
constexpr int W1HI = 0,       W1LO = 122880;
constexpr int W2HI = 245760,  W2LO = 286720;
constexpr int W3HI = 327680,  W3LO = 352256;
constexpr int WNET = 376832;

__device__ int g_cnt[S_];
__device__ int g_idx[S_ * NMAX];
__device__ double g_sum;
__device__ int g_done;
__device__ __align__(16) unsigned char g_wimg[32L * WNET];

__device__ __forceinline__ float celu_f(float x) {
    return x > 0.0f ? x : 0.1f * expm1f(x * 10.0f);
}
__device__ __forceinline__ uint32_t pack_hi(float a, float b, float& ra, float& rb) {
    __nv_bfloat16 ha = __float2bfloat16(a), hb = __float2bfloat16(b);
    ra = a - __bfloat162float(ha); rb = b - __bfloat162float(hb);
    return (uint32_t)__bfloat16_as_ushort(ha) | ((uint32_t)__bfloat16_as_ushort(hb) << 16);
}
__device__ __forceinline__ uint32_t pack_bf(float a, float b) {
    return (uint32_t)__bfloat16_as_ushort(__float2bfloat16(a))
         | ((uint32_t)__bfloat16_as_ushort(__float2bfloat16(b)) << 16);
}
__device__ __forceinline__ void cp16(char* d, const void* s) {
    asm volatile("cp.async.cg.shared.global [%0], [%1], 16;\n"
        :: "r"((uint32_t)__cvta_generic_to_shared(d)), "l"(s));
}
__device__ __forceinline__ void mma4(float* c, uint32_t a0, uint32_t a1, uint32_t a2,
                                     uint32_t a3, uint32_t b0, uint32_t b1) {
    asm volatile("mma.sync.aligned.m16n8k16.row.col.f32.bf16.bf16.f32 "
        "{%0,%1,%2,%3},{%4,%5,%6,%7},{%8,%9},{%0,%1,%2,%3};"
        : "+f"(c[0]), "+f"(c[1]), "+f"(c[2]), "+f"(c[3])
        : "r"(a0), "r"(a1), "r"(a2), "r"(a3), "r"(b0), "r"(b1));
}
__device__ __forceinline__ void ldsm4(uint32_t& r0, uint32_t& r1, uint32_t& r2,
                                      uint32_t& r3, uint32_t addr) {
    asm volatile("ldmatrix.sync.aligned.m8n8.x4.shared.b16 {%0,%1,%2,%3}, [%4];"
        : "=r"(r0), "=r"(r1), "=r"(r2), "=r"(r3) : "r"(addr));
}
__device__ __forceinline__ void ldsm2(uint32_t& r0, uint32_t& r1, uint32_t addr) {
    asm volatile("ldmatrix.sync.aligned.m8n8.x2.shared.b16 {%0,%1}, [%2];"
        : "=r"(r0), "=r"(r1) : "r"(addr));
}

__global__ void k_cvt_w(const float* __restrict__ W1, const float* __restrict__ W2,
                        const float* __restrict__ W3) {
    int se = blockIdx.x, tid = threadIdx.x;
    unsigned char* nb = g_wimg + (long)se * WNET;
    for (int i = tid; i < (D0 / 2) * D1; i += 256) {
        int n = i % D1, k = 2 * (i / D1);
        float r0, r1;
        uint32_t h = pack_hi(W1[((long)se * D0 + k) * D1 + n],
                             W1[((long)se * D0 + k + 1) * D1 + n], r0, r1);
        uint32_t o = (uint32_t)(n * D0 + k) * 2;
        *(uint32_t*)(nb + W1HI + o) = h;
        *(uint32_t*)(nb + W1LO + o) = pack_bf(r0, r1);
    }
    for (int i = tid; i < (D1 / 2) * D2; i += 256) {
        int n = i % D2, k = 2 * (i / D2);
        float r0, r1;
        uint32_t h = pack_hi(W2[((long)se * D1 + k) * D2 + n],
                             W2[((long)se * D1 + k + 1) * D2 + n], r0, r1);
        uint32_t o = (uint32_t)(n * D1 + k) * 2;
        *(uint32_t*)(nb + W2HI + o) = h;
        *(uint32_t*)(nb + W2LO + o) = pack_bf(r0, r1);
    }
    for (int i = tid; i < (D2 / 2) * D3; i += 256) {
        int n = i % D3, k = 2 * (i / D3);
        float r0, r1;
        uint32_t h = pack_hi(W3[((long)se * D2 + k) * D3 + n],
                             W3[((long)se * D2 + k + 1) * D3 + n], r0, r1);
        uint32_t o = (uint32_t)(n * D2 + k) * 2;
        *(uint32_t*)(nb + W3HI + o) = h;
        *(uint32_t*)(nb + W3LO + o) = pack_bf(r0, r1);
    }
}

__global__ void k_bin(const int* __restrict__ species, int n) {
    int i = blockIdx.x * blockDim.x + threadIdx.x;
    int lane = threadIdx.x & 31;
    unsigned active = __ballot_sync(0xffffffffu, i < n);
    if (i < n) {
        int s = species[i] & (S_ - 1);
        unsigned peers = __match_any_sync(active, s);
        int leader = __ffs(peers) - 1;
        int rank = __popc(peers & ((1u << lane) - 1));
        int b = 0;
        if (lane == leader) b = atomicAdd(&g_cnt[s], __popc(peers));
        b = __shfl_sync(peers, b, leader);
        g_idx[s * NMAX + b + rank] = i;
    }
}

__global__ void k_pad() {}

// Stage one K32 weight chunk (hi+lo) into buf: [n][40 elems] per split.
template<int K, int N>
__device__ __forceinline__ void stage(char* buf, const unsigned char* gHi,
                                      const unsigned char* gLo, int c, int tid) {
    for (int i = tid; i < N * 4; i += NT) {
        int n = i >> 2, h = (i & 3) << 4;
        cp16(buf + n * 80 + h,        gHi + (long)n * K * 2 + c * 64 + h);
        cp16(buf + WSPL + n * 80 + h, gLo + (long)n * K * 2 + c * 64 + h);
    }
    asm volatile("cp.async.commit_group;\n");
}

// One layer. INVARIANT at entry: this layer's chunk 0 staged into wb[p]
// (group committed, possibly in flight). At exit: next image's chunk 0
// (nxHi/nxLo, sizes NK/NN) staged into wb[p] likewise, if nxHi != null.
// NO trailing syncthreads — next consumer's first wait+sync covers it.
template<int K, int N, int PIN, int POUT, int NK, int NN>
__device__ __forceinline__ void mma_layer(char* sm, uint32_t smA, int aHi, int aLo,
        const unsigned char* gHi, const unsigned char* gLo,
        const unsigned char* nxHi, const unsigned char* nxLo,
        int oHi, int oLo, const float* __restrict__ bias,
        int& p, int tid, int lane, int wid) {
    constexpr int CH = K / 32, NTL = N / 32;
    const int m0 = (wid & 3) << 4, ng = wid >> 2;
    const int r = lane >> 2, cq = (lane & 3) * 2;

    // ldmatrix per-lane bases
    const uint32_t aBase = (uint32_t)(((m0 + ((lane >> 3) & 1) * 8 + (lane & 7)) * PIN
                                      + ((lane >> 4) & 1) * 8) * 2);
    const uint32_t aHiA = smA + aHi + aBase, aLoA = smA + aLo + aBase;
    const uint32_t bBase = (uint32_t)((lane & 7) * 80 + ((lane >> 3) & 1) * 16);

    float acc[NTL][4];
#pragma unroll
    for (int t = 0; t < NTL; t++)
#pragma unroll
        for (int j = 0; j < 4; j++) acc[t][j] = 0.f;

    for (int c = 0; c < CH; c++) {
        asm volatile("cp.async.wait_group 0;\n");
        __syncthreads();
        if (c + 1 < CH)      stage<K, N>(sm + WB0 + (p ^ 1) * WBUF, gHi, gLo, c + 1, tid);
        else if (nxHi)       stage<NK, NN>(sm + WB0 + (p ^ 1) * WBUF, nxHi, nxLo, 0, tid);
        const uint32_t bufHA = smA + WB0 + p * WBUF;
        const uint32_t bufLA = bufHA + WSPL;
#pragma unroll
        for (int sh = 0; sh < 2; sh++) {
            uint32_t kb = (uint32_t)((2 * c + sh) * 32);   // bytes: 16 elems
            uint32_t a0, a1, a2, a3, l0, l1, l2, l3;
            ldsm4(a0, a1, a2, a3, aHiA + kb);
            ldsm4(l0, l1, l2, l3, aLoA + kb);
#pragma unroll
            for (int nt = 0; nt < NTL; nt++) {
                uint32_t bo = (uint32_t)((ng * (N / 4) + nt * 8) * 80) + bBase + sh * 32;
                uint32_t bh0, bh1, bl0, bl1;
                ldsm2(bh0, bh1, bufHA + bo);
                ldsm2(bl0, bl1, bufLA + bo);
                mma4(acc[nt], a0, a1, a2, a3, bh0, bh1);
                mma4(acc[nt], l0, l1, l2, l3, bh0, bh1);
                mma4(acc[nt], a0, a1, a2, a3, bl0, bl1);
            }
        }
        p ^= 1;
    }
    // epilogue: bias + CELU -> split hi/lo -> next A-image
#pragma unroll
    for (int nt = 0; nt < NTL; nt++) {
        int col = ng * (N / 4) + nt * 8 + cq;
        float b0 = bias[col], b1 = bias[col + 1];
        float h00 = celu_f(acc[nt][0] + b0), h01 = celu_f(acc[nt][1] + b1);
        float h10 = celu_f(acc[nt][2] + b0), h11 = celu_f(acc[nt][3] + b1);
        float r0, r1;
        uint32_t w0 = pack_hi(h00, h01, r0, r1);
        uint32_t w0l = pack_bf(r0, r1);
        uint32_t w1 = pack_hi(h10, h11, r0, r1);
        uint32_t w1l = pack_bf(r0, r1);
        int o0 = ((m0 + r) * POUT + col) * 2, o1 = ((m0 + r + 8) * POUT + col) * 2;
        *(uint32_t*)(sm + oHi + o0) = w0;  *(uint32_t*)(sm + oLo + o0) = w0l;
        *(uint32_t*)(sm + oHi + o1) = w1;  *(uint32_t*)(sm + oLo + o1) = w1l;
    }
}

__global__ void __launch_bounds__(NT, 1)
k_compute(const float* __restrict__ aev,
          const float* __restrict__ B1, const float* __restrict__ B2,
          const float* __restrict__ B3, const float* __restrict__ W4,
          const float* __restrict__ B4, float* __restrict__ out) {
    extern __shared__ char sm[];
    const uint32_t smA = (uint32_t)__cvta_generic_to_shared(sm);
    const int tid = threadIdx.x, lane = tid & 31, wid = tid >> 5;
    float* sBias  = (float*)(sm + OF_BIAS);
    float* sW4    = (float*)(sm + OF_W4);
    float* sAtomE = (float*)(sm + OF_AE);
    int*   sIdx   = (int*)(sm + OF_IDX);

    // 1-D work list: map blockIdx.x -> (species, tile)
    int c0 = g_cnt[0], c1 = g_cnt[1], c2 = g_cnt[2], c3 = g_cnt[3];
    int t0 = (c0 + TM - 1) / TM, t1 = (c1 + TM - 1) / TM, t2 = (c2 + TM - 1) / TM;
    int t3 = (c3 + TM - 1) / TM;
    int w = blockIdx.x, s = -1, tx = 0, cnt = 0;
    if (w < t0)                    { s = 0; tx = w;                cnt = c0; }
    else if (w < t0 + t1)          { s = 1; tx = w - t0;           cnt = c1; }
    else if (w < t0 + t1 + t2)     { s = 2; tx = w - t0 - t1;      cnt = c2; }
    else if (w < t0 + t1 + t2 + t3){ s = 3; tx = w - t0 - t1 - t2; cnt = c3; }

    if (s >= 0) {
        const int base = tx * TM;
        const int nvalid = min(TM, cnt - base);
        if (tid < TM) {
            sIdx[tid] = g_idx[s * NMAX + base + min(tid, nvalid - 1)];
            sAtomE[tid] = 0.f;
        }
        __syncthreads();

        const unsigned char* wn0 = g_wimg + (long)(s * E_) * WNET;
        // head of pipeline: stage W1(e=0) chunk 0 (overlaps A-image build)
        stage<D0, D1>(sm + WB0, wn0 + W1HI, wn0 + W1LO, 0, tid);

        // AEV -> bf16 hi/lo A-image (once per tile)
        for (int i = tid; i < TM * (D0 / 2); i += NT) {
            int rr = i / (D0 / 2), k = 2 * (i % (D0 / 2));
            float2 v = *(const float2*)(aev + (long)sIdx[rr] * D0 + k);
            float r0, r1;
            uint32_t h = pack_hi(v.x, v.y, r0, r1);
            int o = (rr * PA + k) * 2;
            *(uint32_t*)(sm + A_HI + o) = h;
            *(uint32_t*)(sm + A_LO + o) = pack_bf(r0, r1);
        }

        int p = 0;
        for (int e = 0; e < E_; e++) {
            const unsigned char* wn = wn0 + (long)e * WNET;
            const unsigned char* wnN = (e + 1 < E_) ? wn + WNET : nullptr;
            const int se = s * E_ + e;
            for (int t = tid; t < 480; t += NT) {
                if (t < D1)       sBias[t] = B1[se * D1 + t];
                else if (t < 288) sBias[t] = B2[se * D2 + t - D1];
                else if (t < 384) sBias[t] = B3[se * D3 + t - 288];
                else              sW4[t - 384] = W4[se * D3 + t - 384];
            }
            __syncthreads();

            mma_layer<D0, D1, PA, P1, D1, D2>(sm, smA, A_HI, A_LO,
                wn + W1HI, wn + W1LO, wn + W2HI, wn + W2LO,
                H1_HI, H1_LO, sBias, p, tid, lane, wid);
            mma_layer<D1, D2, P1, P2, D2, D3>(sm, smA, H1_HI, H1_LO,
                wn + W2HI, wn + W2LO, wn + W3HI, wn + W3LO,
                H2_HI, H2_LO, sBias + D1, p, tid, lane, wid);
            mma_layer<D2, D3, P2, P3, D0, D1>(sm, smA, H2_HI, H2_LO,
                wn + W3HI, wn + W3LO,
                wnN ? wnN + W1HI : nullptr, wnN ? wnN + W1LO : nullptr,
                H3_HI, H3_LO, sBias + 288, p, tid, lane, wid);
            __syncthreads();   // H3 image complete before L4 reads

            // layer 4: per-atom dot(h3, w4); 8 threads per atom
            {
                int atom = tid >> 3, q = tid & 7;
                float v = 0.f;
#pragma unroll
                for (int m = 0; m < 12; m += 2) {
                    int k = q * 12 + m;
                    uint32_t hw = *(uint32_t*)(sm + H3_HI + (atom * P3 + k) * 2);
                    uint32_t lw = *(uint32_t*)(sm + H3_LO + (atom * P3 + k) * 2);
                    float x0 = __bfloat162float(__ushort_as_bfloat16((unsigned short)(hw & 0xffff)))
                             + __bfloat162float(__ushort_as_bfloat16((unsigned short)(lw & 0xffff)));
                    float x1 = __bfloat162float(__ushort_as_bfloat16((unsigned short)(hw >> 16)))
                             + __bfloat162float(__ushort_as_bfloat16((unsigned short)(lw >> 16)));
                    v += x0 * sW4[k] + x1 * sW4[k + 1];
                }
                v += __shfl_xor_sync(0xffffffffu, v, 1);
                v += __shfl_xor_sync(0xffffffffu, v, 2);
                v += __shfl_xor_sync(0xffffffffu, v, 4);
                if (q == 0) sAtomE[atom] += v;
                __syncthreads();
            }
        }

        // reduce valid atoms; + sum of b4 per atom; mean over E
        if (tid < 32) {
            float sb4 = 0.f;
            for (int e = 0; e < E_; e++) sb4 += __ldg(B4 + s * E_ + e);
            float v = 0.f;
            for (int t = tid; t < nvalid; t += 32) v += sAtomE[t] + sb4;
#pragma unroll
            for (int o = 16; o > 0; o >>= 1) v += __shfl_down_sync(0xffffffffu, v, o);
            if (tid == 0) atomicAdd(&g_sum, (double)v * 0.125);
        }
        asm volatile("cp.async.wait_group 0;\n");   // drain any tail stage
    }

    if (tid == 0) {
        __threadfence();
        int total = gridDim.x;
        if (atomicAdd(&g_done, 1) == total - 1) {
            double v = atomicAdd(&g_sum, 0.0);
            out[0] = (float)v;
            g_sum = 0.0;
            g_done = 0;
            for (int i = 0; i < S_; i++) g_cnt[i] = 0;
            __threadfence();
        }
    }
}

extern "C" void kernel_launch(void* const* d_in, const int* in_sizes, int n_in,
                              void* d_out, int out_size) {
    const float* aev     = (const float*)d_in[0];
    const int*   species = (const int*)  d_in[1];
    const float* W1 = (const float*)d_in[2];
    const float* B1 = (const float*)d_in[3];
    const float* W2 = (const float*)d_in[4];
    const float* B2 = (const float*)d_in[5];
    const float* W3 = (const float*)d_in[6];
    const float* B3 = (const float*)d_in[7];
    const float* W4 = (const float*)d_in[8];
    const float* B4 = (const float*)d_in[9];
    float* out = (float*)d_out;

    int n = in_sizes[1];
    if (n > NMAX) n = NMAX;

    cudaFuncSetAttribute(k_compute, cudaFuncAttributeMaxDynamicSharedMemorySize, SMEMSZ);

    k_cvt_w<<<32, 256>>>(W1, W2, W3);
    k_bin<<<(n + 511) / 512, 512>>>(species, n);
    k_pad<<<1, 32>>>();
    const int blocks = (n + TM - 1) / TM + (S_ - 1);
    k_compute<<<blocks, NT, SMEMSZ>>>(aev, B1, B2, B3, W4, B4, out);
}